// round 14
// baseline (speedup 1.0000x reference)
#include <cuda_runtime.h>
#include <math.h>

#define BB 8
#define TT 8192
#define DD 1024
#define HH 16
#define HDIM 64
#define NSPLIT 32
#define CHUNK 256

#define NEG_INF (-__int_as_float(0x7f800000) * 1.0f)

// Scratch (static __device__ arrays — no allocation allowed)
__device__ float g_qkv[BB * 3 * DD];                 // [B, 3D]
__device__ float g_part[BB * HH * NSPLIT * 66];      // per-split: m, l, acc[64]
__device__ int   g_cnt[BB * HH];                     // arrival counters (self-resetting)

// ---------------------------------------------------------------------------
// Init: qkv = bias (broadcast), and seed out's y region with b_proj
__global__ void init_qkv_kernel(const float* __restrict__ b_attn,
                                const float* __restrict__ b_proj,
                                float* __restrict__ out) {
    int i = blockIdx.x * blockDim.x + threadIdx.x;
    if (i < BB * 3 * DD) g_qkv[i] = b_attn[i % (3 * DD)];
    if (i < BB * DD) out[i] = b_proj[i % DD];
}

// ---------------------------------------------------------------------------
// Split-K GEMV-batch for qkv: g_qkv[b, j] += sum_i x[b, i] * W_attn[i, j]
// grid.x = N/256 column blocks, grid.y = 64 k-blocks of KB=16.
// W tile staged via 16-byte cp.async.cg (fire-and-forget; ptxas can't
// serialize them).
__global__ void __launch_bounds__(256) gemm_splitk_kernel(
        const float* __restrict__ X,
        const float* __restrict__ W,
        float* __restrict__ out, int N) {
    const int KB = 16;
    const int tid = threadIdx.x;
    const int jb = blockIdx.x * 256;
    const int j = jb + tid;
    const int i0 = blockIdx.y * KB;

    __shared__ float xs[BB * KB];      // 512 B
    __shared__ float ws[KB][256];      // 16 KB

    // async-stage the 16x256 W tile: 1024 float4s, 4 per thread
    unsigned ws_base = (unsigned)__cvta_generic_to_shared(&ws[0][0]);
#pragma unroll
    for (int r = 0; r < 4; r++) {
        int f = r * 256 + tid;            // float4 index
        int row = f >> 6, c4 = f & 63;    // 64 float4 per row
        const float* src = W + (size_t)(i0 + row) * N + jb + c4 * 4;
        asm volatile("cp.async.cg.shared.global [%0], [%1], 16;\n"
                     :: "r"(ws_base + f * 16), "l"(src));
    }
    asm volatile("cp.async.commit_group;\n" ::: "memory");

    // x tile via regular load (tiny; overlaps the async group)
    if (tid < BB * KB) {
        int bb = tid >> 4, ii = tid & 15;
        xs[tid] = X[bb * DD + i0 + ii];
    }

    asm volatile("cp.async.wait_group 0;\n" ::: "memory");
    __syncthreads();

    float acc[BB];
#pragma unroll
    for (int bb = 0; bb < BB; bb++) acc[bb] = 0.f;

#pragma unroll
    for (int ii = 0; ii < KB; ii++) {
        float w = ws[ii][tid];
#pragma unroll
        for (int bb = 0; bb < BB; bb++)
            acc[bb] = fmaf(xs[bb * KB + ii], w, acc[bb]);
    }
#pragma unroll
    for (int bb = 0; bb < BB; bb++)
        atomicAdd(&out[bb * N + j], acc[bb]);
}

// ---------------------------------------------------------------------------
// Flash-decoding attention, split over time, with FUSED split-combine AND
// fused output projection: the last block to finish for a given (b,h)
// merges all split partials into y_slice[64], then applies the 64x1024
// W_proj chunk and atomically accumulates into out (seeded with b_proj).
// Also emits k_step/v_step. grid = (NSPLIT, H, B), block = 256 (8 warps).
__global__ void attn_kernel(const float* __restrict__ past_k,
                            const float* __restrict__ past_v,
                            const int* __restrict__ idx,
                            const float* __restrict__ W_proj,
                            float* __restrict__ out) {
    const int split = blockIdx.x, h = blockIdx.y, b = blockIdx.z;
    const int id = idx[b];
    const int start = split * CHUNK;
    if (start > id) return;                       // inactive split: no writes
    const int end = min(start + CHUNK - 1, id);   // inclusive
    const int nact = id / CHUNK + 1;              // number of active splits

    const int tid = threadIdx.x, warp = tid >> 5, lane = tid & 31;
    const int hw = lane >> 4, sub = lane & 15;

    const float* qkv_b = g_qkv + b * 3 * DD;
    float4 q = *(const float4*)(qkv_b + h * HDIM + 4 * sub);
    const float scale = 0.125f;  // 1/sqrt(64)
    q.x *= scale; q.y *= scale; q.z *= scale; q.w *= scale;

    float m = -1e30f, l = 0.f;
    float4 acc = make_float4(0.f, 0.f, 0.f, 0.f);

    int t = start + 2 * warp + hw;
    bool valid = (t <= end);
    float4 kk = make_float4(0.f, 0.f, 0.f, 0.f);
    float4 vv = make_float4(0.f, 0.f, 0.f, 0.f);
    if (valid) {
        size_t off = (((size_t)b * TT + t) * HH + h) * HDIM;
        const float* kp = (t == id) ? (qkv_b + DD + h * HDIM) : (past_k + off);
        const float* vp = (t == id) ? (qkv_b + 2 * DD + h * HDIM) : (past_v + off);
        kk = *(const float4*)(kp + 4 * sub);
        vv = *(const float4*)(vp + 4 * sub);
    }

    while (__ballot_sync(0xffffffffu, valid)) {
        int tn = t + 16;
        bool nvalid = (tn <= end);
        float4 kn = make_float4(0.f, 0.f, 0.f, 0.f);
        float4 vn = make_float4(0.f, 0.f, 0.f, 0.f);
        if (nvalid) {  // prefetch next K/V while computing current
            size_t off = (((size_t)b * TT + tn) * HH + h) * HDIM;
            const float* kp = (tn == id) ? (qkv_b + DD + h * HDIM) : (past_k + off);
            const float* vp = (tn == id) ? (qkv_b + 2 * DD + h * HDIM) : (past_v + off);
            kn = *(const float4*)(kp + 4 * sub);
            vn = *(const float4*)(vp + 4 * sub);
        }

        float s = q.x * kk.x + q.y * kk.y + q.z * kk.z + q.w * kk.w;
#pragma unroll
        for (int o = 8; o; o >>= 1) s += __shfl_xor_sync(0xffffffffu, s, o);
        if (!valid) s = NEG_INF;   // dead half-warp contributes p = 0

        float mn = fmaxf(m, s);    // m >= -1e30 always, so mn finite
        float c = __expf(m - mn);
        float p = __expf(s - mn);  // 0 for invalid lanes
        l = l * c + p;
        acc.x = acc.x * c + p * vv.x;
        acc.y = acc.y * c + p * vv.y;
        acc.z = acc.z * c + p * vv.z;
        acc.w = acc.w * c + p * vv.w;
        m = mn;

        kk = kn; vv = vn; t = tn; valid = nvalid;
    }

    // merge the two half-warps (dims match: both halves hold dims 4*sub..)
    {
        float mo = __shfl_xor_sync(0xffffffffu, m, 16);
        float lo = __shfl_xor_sync(0xffffffffu, l, 16);
        float4 ao;
        ao.x = __shfl_xor_sync(0xffffffffu, acc.x, 16);
        ao.y = __shfl_xor_sync(0xffffffffu, acc.y, 16);
        ao.z = __shfl_xor_sync(0xffffffffu, acc.z, 16);
        ao.w = __shfl_xor_sync(0xffffffffu, acc.w, 16);
        float M = fmaxf(m, mo);
        float e1 = __expf(m - M), e2 = __expf(mo - M);
        l = l * e1 + lo * e2;
        acc.x = acc.x * e1 + ao.x * e2;
        acc.y = acc.y * e1 + ao.y * e2;
        acc.z = acc.z * e1 + ao.z * e2;
        acc.w = acc.w * e1 + ao.w * e2;
        m = M;
    }

    // merge 8 warps via shared memory
    __shared__ float sm[8], sl[8];
    __shared__ float4 sa[8][16];
    if (lane == 0) { sm[warp] = m; sl[warp] = l; }
    if (hw == 0) sa[warp][sub] = acc;
    __syncthreads();

    float* part_base0 = &g_part[((size_t)b * HH + h) * NSPLIT * 66];
    if (tid < HDIM) {
        float M = -1e30f;
#pragma unroll
        for (int w = 0; w < 8; w++) M = fmaxf(M, sm[w]);
        float L = 0.f, A = 0.f;
#pragma unroll
        for (int w = 0; w < 8; w++) {
            float e = __expf(sm[w] - M);
            L += e * sl[w];
            A += e * ((const float*)&sa[w][0])[tid];
        }
        float* part = part_base0 + (size_t)split * 66;
        if (tid == 0) { part[0] = M; part[1] = L; }
        part[2 + tid] = A;
    }
    __syncthreads();

    // ---- last-block-done: the final arriving block combines all splits ----
    __shared__ int is_last;
    if (tid == 0) {
        __threadfence();                         // publish partials
        int old = atomicAdd(&g_cnt[b * HH + h], 1);
        is_last = (old == nact - 1);
        if (is_last) g_cnt[b * HH + h] = 0;      // self-reset for next replay
    }
    __syncthreads();
    if (!is_last) return;

    // stage all active partials into smem with parallel (high-MLP) loads
    __shared__ float sp[NSPLIT * 66];
    int tot = nact * 66;
    for (int i = tid; i < tot; i += 256) sp[i] = part_base0[i];
    __syncthreads();

    // 4 groups x 64 dims reduction over splits
    int g = tid >> 6;       // 0..3
    int d = tid & 63;

    float M = -1e30f;
    for (int s = g; s < nact; s += 4) M = fmaxf(M, sp[s * 66]);
    float L = 0.f, A = 0.f;
    for (int s = g; s < nact; s += 4) {
        float e = __expf(sp[s * 66] - M);
        L += e * sp[s * 66 + 1];
        A += e * sp[s * 66 + 2 + d];
    }

    __shared__ float shm[4], shl[4], sha[4][HDIM];
    __shared__ float ys[HDIM];
    if (d == 0) { shm[g] = M; shl[g] = L; }
    sha[g][d] = A;
    __syncthreads();

    int j = h * HDIM + d;
    if (g == 0) {
        float MM = fmaxf(fmaxf(shm[0], shm[1]), fmaxf(shm[2], shm[3]));
        float LL = 0.f, AA = 0.f;
#pragma unroll
        for (int gg = 0; gg < 4; gg++) {
            float e = __expf(shm[gg] - MM);
            LL += e * shl[gg];
            AA += e * sha[gg][d];
        }
        ys[d] = AA / LL;               // y_attn slice for (b, h)
    } else if (g == 2) {
        out[BB * DD + b * DD + j] = qkv_b[DD + j];                     // k_step
    } else if (g == 3) {
        out[2 * BB * DD + b * DD + j] = qkv_b[2 * DD + j];             // v_step
    }
    __syncthreads();

    // ---- fused output projection: out[b, :] += ys @ W_proj[h*64:(h+1)*64, :]
    // Each thread owns 4 columns (float4). 16-deep load batches for MLP.
    {
        const float4* Wp4 = (const float4*)(W_proj + (size_t)h * HDIM * DD);
        float4 a4 = make_float4(0.f, 0.f, 0.f, 0.f);
#pragma unroll
        for (int k0 = 0; k0 < HDIM; k0 += 16) {
            float4 w[16];
#pragma unroll
            for (int u = 0; u < 16; u++)
                w[u] = Wp4[(size_t)(k0 + u) * 256 + tid];
#pragma unroll
            for (int u = 0; u < 16; u++) {
                float y = ys[k0 + u];
                a4.x = fmaf(y, w[u].x, a4.x);
                a4.y = fmaf(y, w[u].y, a4.y);
                a4.z = fmaf(y, w[u].z, a4.z);
                a4.w = fmaf(y, w[u].w, a4.w);
            }
        }
        float* op = out + b * DD + tid * 4;
        atomicAdd(op + 0, a4.x);
        atomicAdd(op + 1, a4.y);
        atomicAdd(op + 2, a4.z);
        atomicAdd(op + 3, a4.w);
    }
}

// ---------------------------------------------------------------------------
extern "C" void kernel_launch(void* const* d_in, const int* in_sizes, int n_in,
                              void* d_out, int out_size) {
    const float* x      = (const float*)d_in[0];
    const float* past_k = (const float*)d_in[1];
    const float* past_v = (const float*)d_in[2];
    const int*   idx    = (const int*)d_in[3];
    const float* W_attn = (const float*)d_in[4];
    const float* b_attn = (const float*)d_in[5];
    const float* W_proj = (const float*)d_in[6];
    const float* b_proj = (const float*)d_in[7];
    float* out = (float*)d_out;

    float* qkv_ptr = nullptr;
    cudaGetSymbolAddress((void**)&qkv_ptr, g_qkv);

    // 1. qkv = bias; out y-region = b_proj
    init_qkv_kernel<<<24, 1024>>>(b_attn, b_proj, out);
    // 2. qkv += x @ W_attn   (split-K 64x16, float4 cp.async staging)
    gemm_splitk_kernel<<<dim3(12, 64), 256>>>(x, W_attn, qkv_ptr, 3 * DD);
    // 3. flash-decode attention + fused combine + fused output projection
    attn_kernel<<<dim3(NSPLIT, HH, BB), 256>>>(past_k, past_v, idx, W_proj, out);
}

// round 17
// speedup vs baseline: 1.1410x; 1.1410x over previous
#include <cuda_runtime.h>
#include <math.h>

#define BB 8
#define TT 8192
#define DD 1024
#define HH 16
#define HDIM 64
#define NSPLIT 32
#define CHUNK 256

#define NEG_INF (-__int_as_float(0x7f800000) * 1.0f)

// Scratch (static __device__ arrays — no allocation allowed).
// INVARIANT: g_qkv is all-zero at kernel_launch entry. It starts zeroed
// (CUDA zero-init) and the attn epilogue re-zeroes every slice it consumed,
// restoring the invariant for the next call/replay.
__device__ float g_qkv[BB * 3 * DD];                 // [B, 3D]
__device__ float g_part[BB * HH * NSPLIT * 66];      // per-split: m, l, acc[64]
__device__ float g_yattn[BB * DD];                   // [B, H*HD]
__device__ int   g_cnt[BB * HH];                     // arrival counters (self-resetting)

// ---------------------------------------------------------------------------
// Split-K GEMV-batch: out[b, j] += sum_i X[b, i] * W[i, j]   (Kdim = 1024)
// grid.x = N/256 column blocks, grid.y = 64 k-blocks of KB=16.
// W tile staged via 16-byte cp.async.cg (fire-and-forget; ptxas can't
// serialize them). The blockIdx.y==0 split also adds the bias (target
// buffer is zero at entry: g_qkv invariant / b_proj-seeded out for gemm2).
__global__ void __launch_bounds__(256) gemm_splitk_kernel(
        const float* __restrict__ X,
        const float* __restrict__ W,
        const float* __restrict__ bias,   // added by the y==0 split (may be null)
        float* __restrict__ out, int N) {
    const int KB = 16;
    const int tid = threadIdx.x;
    const int jb = blockIdx.x * 256;
    const int j = jb + tid;
    const int i0 = blockIdx.y * KB;

    __shared__ float xs[BB * KB];      // 512 B
    __shared__ float ws[KB][256];      // 16 KB

    // async-stage the 16x256 W tile: 1024 float4s, 4 per thread
    unsigned ws_base = (unsigned)__cvta_generic_to_shared(&ws[0][0]);
#pragma unroll
    for (int r = 0; r < 4; r++) {
        int f = r * 256 + tid;            // float4 index
        int row = f >> 6, c4 = f & 63;    // 64 float4 per row
        const float* src = W + (size_t)(i0 + row) * N + jb + c4 * 4;
        asm volatile("cp.async.cg.shared.global [%0], [%1], 16;\n"
                     :: "r"(ws_base + f * 16), "l"(src));
    }
    asm volatile("cp.async.commit_group;\n" ::: "memory");

    // x tile via regular load (tiny; overlaps the async group)
    if (tid < BB * KB) {
        int bb = tid >> 4, ii = tid & 15;
        xs[tid] = X[bb * DD + i0 + ii];
    }

    asm volatile("cp.async.wait_group 0;\n" ::: "memory");
    __syncthreads();

    float acc[BB];
    float seed = (blockIdx.y == 0 && bias) ? bias[j] : 0.f;
#pragma unroll
    for (int bb = 0; bb < BB; bb++) acc[bb] = seed;

#pragma unroll
    for (int ii = 0; ii < KB; ii++) {
        float w = ws[ii][tid];
#pragma unroll
        for (int bb = 0; bb < BB; bb++)
            acc[bb] = fmaf(xs[bb * KB + ii], w, acc[bb]);
    }
#pragma unroll
    for (int bb = 0; bb < BB; bb++)
        atomicAdd(&out[bb * N + j], acc[bb]);
}

// ---------------------------------------------------------------------------
// Flash-decoding attention, split over time, with FUSED split-combine:
// the last block to finish for a given (b,h) merges all split partials,
// writes y_attn, emits k_step/v_step + b_proj seed to out, then ZEROES the
// consumed g_qkv slices (restoring the zero-at-entry invariant).
// grid = (NSPLIT, H, B), block = 256 (8 warps).
__global__ void attn_kernel(const float* __restrict__ past_k,
                            const float* __restrict__ past_v,
                            const int* __restrict__ idx,
                            const float* __restrict__ b_proj,
                            float* __restrict__ out) {
    const int split = blockIdx.x, h = blockIdx.y, b = blockIdx.z;
    const int id = idx[b];
    const int start = split * CHUNK;
    if (start > id) return;                       // inactive split: no writes
    const int end = min(start + CHUNK - 1, id);   // inclusive
    const int nact = id / CHUNK + 1;              // number of active splits

    const int tid = threadIdx.x, warp = tid >> 5, lane = tid & 31;
    const int hw = lane >> 4, sub = lane & 15;

    float* qkv_b = g_qkv + b * 3 * DD;
    float4 q = *(const float4*)(qkv_b + h * HDIM + 4 * sub);
    const float scale = 0.125f;  // 1/sqrt(64)
    q.x *= scale; q.y *= scale; q.z *= scale; q.w *= scale;

    float m = -1e30f, l = 0.f;
    float4 acc = make_float4(0.f, 0.f, 0.f, 0.f);

    int t = start + 2 * warp + hw;
    bool valid = (t <= end);
    float4 kk = make_float4(0.f, 0.f, 0.f, 0.f);
    float4 vv = make_float4(0.f, 0.f, 0.f, 0.f);
    if (valid) {
        size_t off = (((size_t)b * TT + t) * HH + h) * HDIM;
        const float* kp = (t == id) ? (qkv_b + DD + h * HDIM) : (past_k + off);
        const float* vp = (t == id) ? (qkv_b + 2 * DD + h * HDIM) : (past_v + off);
        kk = *(const float4*)(kp + 4 * sub);
        vv = *(const float4*)(vp + 4 * sub);
    }

    while (__ballot_sync(0xffffffffu, valid)) {
        int tn = t + 16;
        bool nvalid = (tn <= end);
        float4 kn = make_float4(0.f, 0.f, 0.f, 0.f);
        float4 vn = make_float4(0.f, 0.f, 0.f, 0.f);
        if (nvalid) {  // prefetch next K/V while computing current
            size_t off = (((size_t)b * TT + tn) * HH + h) * HDIM;
            const float* kp = (tn == id) ? (qkv_b + DD + h * HDIM) : (past_k + off);
            const float* vp = (tn == id) ? (qkv_b + 2 * DD + h * HDIM) : (past_v + off);
            kn = *(const float4*)(kp + 4 * sub);
            vn = *(const float4*)(vp + 4 * sub);
        }

        float s = q.x * kk.x + q.y * kk.y + q.z * kk.z + q.w * kk.w;
#pragma unroll
        for (int o = 8; o; o >>= 1) s += __shfl_xor_sync(0xffffffffu, s, o);
        if (!valid) s = NEG_INF;   // dead half-warp contributes p = 0

        float mn = fmaxf(m, s);    // m >= -1e30 always, so mn finite
        float c = __expf(m - mn);
        float p = __expf(s - mn);  // 0 for invalid lanes
        l = l * c + p;
        acc.x = acc.x * c + p * vv.x;
        acc.y = acc.y * c + p * vv.y;
        acc.z = acc.z * c + p * vv.z;
        acc.w = acc.w * c + p * vv.w;
        m = mn;

        kk = kn; vv = vn; t = tn; valid = nvalid;
    }

    // merge the two half-warps (dims match: both halves hold dims 4*sub..)
    {
        float mo = __shfl_xor_sync(0xffffffffu, m, 16);
        float lo = __shfl_xor_sync(0xffffffffu, l, 16);
        float4 ao;
        ao.x = __shfl_xor_sync(0xffffffffu, acc.x, 16);
        ao.y = __shfl_xor_sync(0xffffffffu, acc.y, 16);
        ao.z = __shfl_xor_sync(0xffffffffu, acc.z, 16);
        ao.w = __shfl_xor_sync(0xffffffffu, acc.w, 16);
        float M = fmaxf(m, mo);
        float e1 = __expf(m - M), e2 = __expf(mo - M);
        l = l * e1 + lo * e2;
        acc.x = acc.x * e1 + ao.x * e2;
        acc.y = acc.y * e1 + ao.y * e2;
        acc.z = acc.z * e1 + ao.z * e2;
        acc.w = acc.w * e1 + ao.w * e2;
        m = M;
    }

    // merge 8 warps via shared memory
    __shared__ float sm[8], sl[8];
    __shared__ float4 sa[8][16];
    if (lane == 0) { sm[warp] = m; sl[warp] = l; }
    if (hw == 0) sa[warp][sub] = acc;
    __syncthreads();

    float* part_base0 = &g_part[((size_t)b * HH + h) * NSPLIT * 66];
    if (tid < HDIM) {
        float M = -1e30f;
#pragma unroll
        for (int w = 0; w < 8; w++) M = fmaxf(M, sm[w]);
        float L = 0.f, A = 0.f;
#pragma unroll
        for (int w = 0; w < 8; w++) {
            float e = __expf(sm[w] - M);
            L += e * sl[w];
            A += e * ((const float*)&sa[w][0])[tid];
        }
        float* part = part_base0 + (size_t)split * 66;
        if (tid == 0) { part[0] = M; part[1] = L; }
        part[2 + tid] = A;
    }
    __syncthreads();

    // ---- last-block-done: the final arriving block combines all splits ----
    __shared__ int is_last;
    if (tid == 0) {
        __threadfence();                         // publish partials
        int old = atomicAdd(&g_cnt[b * HH + h], 1);
        is_last = (old == nact - 1);
        if (is_last) g_cnt[b * HH + h] = 0;      // self-reset for next replay
    }
    __syncthreads();
    if (!is_last) return;

    // stage all active partials into smem with parallel (high-MLP) loads
    __shared__ float sp[NSPLIT * 66];
    int tot = nact * 66;
    for (int i = tid; i < tot; i += 256) sp[i] = part_base0[i];
    __syncthreads();

    // 4 groups x 64 dims reduction over splits
    int g = tid >> 6;       // 0..3
    int d = tid & 63;

    float M = -1e30f;
    for (int s = g; s < nact; s += 4) M = fmaxf(M, sp[s * 66]);
    float L = 0.f, A = 0.f;
    for (int s = g; s < nact; s += 4) {
        float e = __expf(sp[s * 66] - M);
        L += e * sp[s * 66 + 1];
        A += e * sp[s * 66 + 2 + d];
    }

    __shared__ float shm[4], shl[4], sha[4][HDIM];
    if (d == 0) { shm[g] = M; shl[g] = L; }
    sha[g][d] = A;
    __syncthreads();

    int j = h * HDIM + d;
    if (g == 0) {
        float MM = fmaxf(fmaxf(shm[0], shm[1]), fmaxf(shm[2], shm[3]));
        float LL = 0.f, AA = 0.f;
#pragma unroll
        for (int gg = 0; gg < 4; gg++) {
            float e = __expf(shm[gg] - MM);
            LL += e * shl[gg];
            AA += e * sha[gg][d];
        }
        g_yattn[b * DD + j] = AA / LL;
    } else if (g == 1) {
        out[b * DD + j] = b_proj[j];                                   // y seed
    } else if (g == 2) {
        out[BB * DD + b * DD + j] = qkv_b[DD + j];                     // k_step
    } else {
        out[2 * BB * DD + b * DD + j] = qkv_b[2 * DD + j];             // v_step
    }
    __syncthreads();

    // restore the g_qkv zero-at-entry invariant for this (b,h)'s slices
    // (all reads of these 192 floats are complete: mainloop q/k/v reads
    // happened before the counter arrival; k/v emission before the barrier)
    if (tid < HDIM) {
        qkv_b[h * HDIM + tid] = 0.f;            // q slice
        qkv_b[DD + h * HDIM + tid] = 0.f;       // k slice
        qkv_b[2 * DD + h * HDIM + tid] = 0.f;   // v slice
    }
}

// ---------------------------------------------------------------------------
extern "C" void kernel_launch(void* const* d_in, const int* in_sizes, int n_in,
                              void* d_out, int out_size) {
    const float* x      = (const float*)d_in[0];
    const float* past_k = (const float*)d_in[1];
    const float* past_v = (const float*)d_in[2];
    const int*   idx    = (const int*)d_in[3];
    const float* W_attn = (const float*)d_in[4];
    const float* b_attn = (const float*)d_in[5];
    const float* W_proj = (const float*)d_in[6];
    const float* b_proj = (const float*)d_in[7];
    float* out = (float*)d_out;

    float* qkv_ptr = nullptr;
    float* yattn_ptr = nullptr;
    cudaGetSymbolAddress((void**)&qkv_ptr, g_qkv);
    cudaGetSymbolAddress((void**)&yattn_ptr, g_yattn);

    // 1. qkv = bias + x @ W_attn  (split-K; y==0 split adds bias; buffer
    //    zero at entry per invariant)
    gemm_splitk_kernel<<<dim3(12, 64), 256>>>(x, W_attn, b_attn, qkv_ptr, 3 * DD);
    // 2. flash-decode attention + fused combine + outputs + invariant restore
    attn_kernel<<<dim3(NSPLIT, HH, BB), 256>>>(past_k, past_v, idx, b_proj, out);
    // 3. y += y_attn @ W_proj   (out already seeded with b_proj)
    gemm_splitk_kernel<<<dim3(4, 64), 256>>>(yattn_ptr, W_proj, nullptr, out, DD);
}